// round 3
// baseline (speedup 1.0000x reference)
#include <cuda_runtime.h>
#include <cstdint>

// C4TransformerVM: the "neural ALU" reference is an exact 4-byte ripple-carry
// adder over one-hot byte encodings (softmax temp=100 over logit gaps >=100
// makes every intermediate exactly one-hot to fp32 precision; deviation
// ~exp(-100) ~ 3.6e-44, vastly below the 1e-3 rel-err threshold).
// So: decode bytes (argmax), 32-bit integer add (final carry discarded, as in
// the reference), emit one-hot result bytes.
// Pure streaming problem: 256 MB read + 128 MB write -> DRAM-bound.

__device__ __forceinline__ int scan8(float4 v0, float4 v1, int base) {
    int idx = 0;
    if (v0.x > 0.5f) idx = base + 0;
    if (v0.y > 0.5f) idx = base + 1;
    if (v0.z > 0.5f) idx = base + 2;
    if (v0.w > 0.5f) idx = base + 3;
    if (v1.x > 0.5f) idx = base + 4;
    if (v1.y > 0.5f) idx = base + 5;
    if (v1.z > 0.5f) idx = base + 6;
    if (v1.w > 0.5f) idx = base + 7;
    return idx;
}

__global__ __launch_bounds__(256) void neural_alu_add_kernel(
    const float* __restrict__ a,
    const float* __restrict__ b,
    float* __restrict__ out,
    int N)
{
    const int warp_id = (blockIdx.x * blockDim.x + threadIdx.x) >> 5;
    const int lane = threadIdx.x & 31;
    if (warp_id >= N) return;
    const size_t n = (size_t)warp_id;

    // ---- Load: 8 rows x 256 floats; each lane grabs 8 contiguous floats.
    // All 16 float4 loads issued up front (MLP ~ 16), streaming (.cs).
    float4 va[8], vb[8];
#pragma unroll
    for (int i = 0; i < 4; i++) {
        const float4* ra = reinterpret_cast<const float4*>(a + ((size_t)i * N + n) * 256);
        const float4* rb = reinterpret_cast<const float4*>(b + ((size_t)i * N + n) * 256);
        va[2 * i]     = __ldcs(ra + lane * 2);
        va[2 * i + 1] = __ldcs(ra + lane * 2 + 1);
        vb[2 * i]     = __ldcs(rb + lane * 2);
        vb[2 * i + 1] = __ldcs(rb + lane * 2 + 1);
    }

    // ---- Decode each byte via warp argmax (identity 0 is also the correct
    // answer when the hot index is 0).
    const int base = lane * 8;
    unsigned int A = 0, B = 0;
#pragma unroll
    for (int i = 0; i < 4; i++) {
        int ia = scan8(va[2 * i], va[2 * i + 1], base);
        int ib = scan8(vb[2 * i], vb[2 * i + 1], base);
        ia = __reduce_max_sync(0xffffffffu, ia);
        ib = __reduce_max_sync(0xffffffffu, ib);
        A |= (unsigned int)ia << (8 * i);
        B |= (unsigned int)ib << (8 * i);
    }

    const unsigned int S = A + B;   // carry out of byte 3 is discarded

    // ---- Write one-hot result rows: 4 rows x 256 floats, 8 floats/lane.
    // Branch-free: float(idx == r) compiles to ISETP+SEL, no BSSY/local mem.
#pragma unroll
    for (int i = 0; i < 4; i++) {
        const int r = (int)((S >> (8 * i)) & 255u);
        float4 w0, w1;
        w0.x = (base + 0 == r) ? 1.0f : 0.0f;
        w0.y = (base + 1 == r) ? 1.0f : 0.0f;
        w0.z = (base + 2 == r) ? 1.0f : 0.0f;
        w0.w = (base + 3 == r) ? 1.0f : 0.0f;
        w1.x = (base + 4 == r) ? 1.0f : 0.0f;
        w1.y = (base + 5 == r) ? 1.0f : 0.0f;
        w1.z = (base + 6 == r) ? 1.0f : 0.0f;
        w1.w = (base + 7 == r) ? 1.0f : 0.0f;
        float4* ro = reinterpret_cast<float4*>(out + ((size_t)i * N + n) * 256);
        __stcs(ro + lane * 2,     w0);
        __stcs(ro + lane * 2 + 1, w1);
    }
}

extern "C" void kernel_launch(void* const* d_in, const int* in_sizes, int n_in,
                              void* d_out, int out_size) {
    const float* a = (const float*)d_in[0];   // [4, N, 256] one-hot
    const float* b = (const float*)d_in[1];   // [4, N, 256] one-hot
    float* out = (float*)d_out;               // [4, N, 256]
    const int N = in_sizes[0] / (4 * 256);

    const int threads = 256;                  // 8 warps/block, 1 warp per n
    const int blocks = (N * 32 + threads - 1) / threads;
    neural_alu_add_kernel<<<blocks, threads>>>(a, b, out, N);
}